// round 6
// baseline (speedup 1.0000x reference)
#include <cuda_runtime.h>
#include <stdint.h>

#define NUM_TNETS 8388608
#define NUM_NODES 1048576

// 2 tnets per thread: int4 pins + float2 weights (best measured shape).
// Streaming loads: evict-first (.cs). Random gathers: L2-only (.cg).
// Binding resource: LTS transaction throughput — ~53M L2 ops / 184 slices
// puts the floor at ~152us; this kernel sits on it.
__global__ void __launch_bounds__(512) scatter_add_kernel(
    const float* __restrict__ beta,          // [1]
    const float* __restrict__ tnet_weights,  // [NUM_TNETS]
    const int*   __restrict__ flat_tnet2pin, // [2*NUM_TNETS] int32
    const int*   __restrict__ pin2node,      // [NUM_PINS]    int32
    float* __restrict__ out)                 // [NUM_NODES]
{
    int t = blockIdx.x * blockDim.x + threadIdx.x;  // pair index: 2 tnets each

    // coalesced 16B streaming load: pins of two arcs [s0,d0,s1,d1]
    int4 pins = __ldcs(reinterpret_cast<const int4*>(flat_tnet2pin) + t);
    // coalesced 8B streaming load: the two arc weights
    float2 wv = __ldcs(reinterpret_cast<const float2*>(tnet_weights) + t);

    float b = __ldg(beta);
    float w0 = wv.x * b;
    float w1 = wv.y * b;

    // four independent random gathers (MLP=4), L2-only
    int n0 = __ldcg(pin2node + pins.x);
    int n1 = __ldcg(pin2node + pins.y);
    int n2 = __ldcg(pin2node + pins.z);
    int n3 = __ldcg(pin2node + pins.w);

    // arc 0 atomics fire as soon as their gathers land; arc 1 follows
    atomicAdd(out + n0, w0);
    atomicAdd(out + n1, w0);
    atomicAdd(out + n2, w1);
    atomicAdd(out + n3, w1);
}

extern "C" void kernel_launch(void* const* d_in, const int* in_sizes, int n_in,
                              void* d_out, int out_size) {
    const float* beta         = (const float*)d_in[0];
    const float* tnet_weights = (const float*)d_in[1];
    const int*   flat_t2p     = (const int*)d_in[2];
    const int*   pin2node     = (const int*)d_in[3];
    float* out = (float*)d_out;

    // 1) zero the poisoned output
    cudaMemsetAsync(out, 0, (size_t)out_size * sizeof(float));

    // 2) gather + atomic scatter-add, beta folded in
    {
        const int threads = 512;
        const int pairs = NUM_TNETS / 2;          // 4,194,304
        const int blocks = pairs / threads;       // 8192 exact
        scatter_add_kernel<<<blocks, threads>>>(beta, tnet_weights, flat_t2p,
                                                pin2node, out);
    }
}

// round 7
// speedup vs baseline: 1.0004x; 1.0004x over previous
#include <cuda_runtime.h>
#include <stdint.h>

#define NUM_TNETS 8388608
#define NUM_NODES 1048576

// FINAL: best measured configuration (152.0us), sitting on the LTS floor.
//
// Roofline model (confirmed by 3 rounds of shape variation):
//   33.5M REDG.ADD (random 4B targets in a 4MB L2-resident output)
// + 16.7M gather sectors (random 4B reads, 84MB L2-resident table)
// + ~3M  streaming sectors (96MB of pins+weights, evict-first)
// = ~53M LTS transactions / 184 slices ~= 289K cyc ~= 152us @ ~1.9GHz.
// L2=82% binding; DRAM=38%, issue=2.4% -- all other pipes slack.
//
// Shape: 2 tnets per thread (int4 pins + float2 weights), 256-thread blocks.
// Streaming loads use .cs (evict-first) to keep the gather table L2-resident;
// gathers use .cg (L2-only) -- ~0% L1 hit rate on random 4B over 84MB.
__global__ void __launch_bounds__(256) scatter_add_kernel(
    const float* __restrict__ beta,          // [1]
    const float* __restrict__ tnet_weights,  // [NUM_TNETS]
    const int*   __restrict__ flat_tnet2pin, // [2*NUM_TNETS] int32
    const int*   __restrict__ pin2node,      // [NUM_PINS]    int32
    float* __restrict__ out)                 // [NUM_NODES]
{
    int t = blockIdx.x * blockDim.x + threadIdx.x;  // pair index: 2 tnets each

    // coalesced 16B streaming load: pins of two arcs [s0,d0,s1,d1]
    int4 pins = __ldcs(reinterpret_cast<const int4*>(flat_tnet2pin) + t);
    // coalesced 8B streaming load: the two arc weights
    float2 wv = __ldcs(reinterpret_cast<const float2*>(tnet_weights) + t);

    float b = __ldg(beta);
    float w0 = wv.x * b;
    float w1 = wv.y * b;

    // four independent random gathers (MLP=4), L2-only
    int n0 = __ldcg(pin2node + pins.x);
    int n1 = __ldcg(pin2node + pins.y);
    int n2 = __ldcg(pin2node + pins.z);
    int n3 = __ldcg(pin2node + pins.w);

    atomicAdd(out + n0, w0);
    atomicAdd(out + n1, w0);
    atomicAdd(out + n2, w1);
    atomicAdd(out + n3, w1);
}

extern "C" void kernel_launch(void* const* d_in, const int* in_sizes, int n_in,
                              void* d_out, int out_size) {
    const float* beta         = (const float*)d_in[0];
    const float* tnet_weights = (const float*)d_in[1];
    const int*   flat_t2p     = (const int*)d_in[2];
    const int*   pin2node     = (const int*)d_in[3];
    float* out = (float*)d_out;

    // 1) zero the poisoned output
    cudaMemsetAsync(out, 0, (size_t)out_size * sizeof(float));

    // 2) gather + atomic scatter-add, beta folded in
    {
        const int threads = 256;
        const int pairs = NUM_TNETS / 2;          // 4,194,304
        const int blocks = pairs / threads;       // 16384 exact
        scatter_add_kernel<<<blocks, threads>>>(beta, tnet_weights, flat_t2p,
                                                pin2node, out);
    }
}